// round 11
// baseline (speedup 1.0000x reference)
#include <cuda_runtime.h>
#include <math.h>
#include <stdint.h>

#define BB 4
#define LL 2048
#define LQ 1024
#define DM 512
#define DIN 1024
#define DSTATE 64
#define NH 16
#define HD 64
#define DXBC 1152
#define ZXW 2176      // z + xBC columns kept in g_zx (row stride)
#define WIN_LD 2192   // full in_proj width (z + xBC + dt)

// ---------------- scratch (device globals; allocation-free) ----------------
__device__ float g_u[2][BB*LL*DM];        // rmsnormed inputs (fp32, for dt path)
__device__ float g_u32[2][BB*LL*DM];      // rmsnormed inputs (tf32-rounded, GEMM A)
__device__ float g_zx[2][BB*LL*ZXW];      // in_proj outputs (z + xBC)
__device__ float g_xbc[2][BB*LL*DXBC];    // conv+silu outputs
__device__ float g_dtT[2][NH*BB*LL];      // dt transposed [h][row]
__device__ float g_dAT[2][NH*BB*LL];      // dA transposed [h][row]
__device__ float g_y[2][BB*LL*DIN];       // scan outputs (+D*x)
__device__ float g_nrm[2][BB*LQ*DIN];     // gated rmsnorm (tf32-rounded)
__device__ float g_fs[BB*LQ*DM];          // factual pre-out-proj (tf32-rounded)
__device__ float g_win32[2][DM*ZXW];      // tf32 weights
__device__ float g_wout32[2][DIN*DM];
__device__ float g_wo32[DM*DM];

// ---------------- helpers ----------------
__device__ __forceinline__ float silu(float x) { return x / (1.f + expf(-x)); }

__device__ __forceinline__ uint32_t f2tf32(float x) {
    uint32_t r;
    asm("cvt.rna.tf32.f32 %0, %1;" : "=r"(r) : "f"(x));
    return r;
}
__device__ __forceinline__ float tf32r(float x) { return __uint_as_float(f2tf32(x)); }

__device__ __forceinline__ void mma_tf32(float* c, const uint32_t* a, const uint32_t* b) {
    asm volatile("mma.sync.aligned.m16n8k8.row.col.f32.tf32.tf32.f32 "
        "{%0,%1,%2,%3}, {%4,%5,%6,%7}, {%8,%9}, {%0,%1,%2,%3};"
        : "+f"(c[0]), "+f"(c[1]), "+f"(c[2]), "+f"(c[3])
        : "r"(a[0]), "r"(a[1]), "r"(a[2]), "r"(a[3]), "r"(b[0]), "r"(b[1]));
}

__device__ __forceinline__ void cpa16(float* dst, const float* src) {
    uint32_t d = (uint32_t)__cvta_generic_to_shared(dst);
    asm volatile("cp.async.cg.shared.global [%0], [%1], 16;" :: "r"(d), "l"(src));
}
__device__ __forceinline__ void cpa_commit() { asm volatile("cp.async.commit_group;"); }
template<int N> __device__ __forceinline__ void cpa_wait() {
    asm volatile("cp.async.wait_group %0;" :: "n"(N));
}

// ---------------- launch 0: input rmsnorm + weight cvt (fused) -------------
// y==0: prep rows; y==1: flat tf32 weight conversion
#define CVT_TOT (2*DM*ZXW + 2*DIN*DM + DM*DM)
__global__ void __launch_bounds__(128) prep_cvt(
    const float* __restrict__ q, const float* __restrict__ kv,
    const float* __restrict__ fw, const float* __restrict__ cw,
    const float* __restrict__ fWin, const float* __restrict__ cWin,
    const float* __restrict__ fWout, const float* __restrict__ cWout,
    const float* __restrict__ oW)
{
    int t = threadIdx.x;
    if (blockIdx.y == 1) {
        for (int i = blockIdx.x * 128 + t; i < CVT_TOT; i += 16384 * 128) {
            int j = i;
            if (j < 2 * DM * ZXW) {
                int reg = j / (DM * ZXW);
                int k = j - reg * (DM * ZXW);
                const float* s = reg ? cWin : fWin;
                int r = k / ZXW, c = k - r * ZXW;
                g_win32[reg][k] = tf32r(s[r * WIN_LD + c]);
            } else if ((j -= 2 * DM * ZXW) < 2 * DIN * DM) {
                int reg = j / (DIN * DM);
                int k = j - reg * (DIN * DM);
                g_wout32[reg][k] = tf32r((reg ? cWout : fWout)[k]);
            } else {
                j -= 2 * DIN * DM;
                g_wo32[j] = tf32r(oW[j]);
            }
        }
        return;
    }

    int row = blockIdx.x;            // 2 * 4 * 2048 rows
    int br  = row >> 13;
    int r   = row & 8191;
    int b   = r >> 11;
    int l   = r & 2047;
    const float* src;
    if (l < LQ) {
        int li = (br == 0) ? l : (LQ - 1 - l);
        src = kv + (b * LQ + li) * DM;
    } else {
        src = q + (b * LQ + (l - LQ)) * DM;
    }
    const float* w = br ? cw : fw;

    float v[4];
    float ss = 0.f;
#pragma unroll
    for (int i = 0; i < 4; i++) { v[i] = src[t + i * 128]; ss += v[i] * v[i]; }

    __shared__ float red[4];
#pragma unroll
    for (int o = 16; o > 0; o >>= 1) ss += __shfl_xor_sync(0xffffffffu, ss, o);
    if ((t & 31) == 0) red[t >> 5] = ss;
    __syncthreads();
    float total = red[0] + red[1] + red[2] + red[3];
    float scale = rsqrtf(total / (float)DM + 1e-5f);

    float* dst   = g_u[br]   + (b * LL + l) * DM;
    float* dst32 = g_u32[br] + (b * LL + l) * DM;
#pragma unroll
    for (int i = 0; i < 4; i++) {
        int idx = t + i * 128;
        float val = v[i] * scale * w[idx];
        dst[idx] = val;
        dst32[idx] = tf32r(val);
    }
}

// ---------------- TF32 GEMM: 128x128x32 tile, 8 warps (64x32), 3-stage -----
#define AS_LD 36
#define BS_LD 136
#define A_STG (128 * AS_LD)    // 4608 floats
#define B_STG (32 * BS_LD)     // 4352 floats
#define B_OFF (3 * A_STG)
#define GEMM_SMEM ((3 * (A_STG + B_STG)) * 4)

__global__ void __launch_bounds__(256) gemm_tf32(
    const float* __restrict__ A0, const float* __restrict__ A1,
    const float* __restrict__ B0, const float* __restrict__ B1,
    float* __restrict__ C0, float* __restrict__ C1,
    const float* __restrict__ bias,
    int M, int N, int K, int lda, int ldb, int ldc, int roundMask)
{
    extern __shared__ float sm[];
    int z = blockIdx.z;
    const float* A = z ? A1 : A0;
    const float* B = z ? B1 : B0;
    float* C = z ? C1 : C0;
    bool rnd = (roundMask >> z) & 1;

    int tid = threadIdx.x;
    int bm = blockIdx.y * 128, bn = blockIdx.x * 128;

    int w = tid >> 5;
    int lane = tid & 31;
    int g = lane >> 2, cq = lane & 3;
    int mw = (w & 1) * 64;
    int nw = (w >> 1) * 32;

    int a_r = tid >> 3, a_c4 = (tid & 7) * 4;
    int b_r = tid >> 5, b_c4 = (tid & 31) * 4;

    const float* Ag = A + (bm + a_r) * lda + a_c4;
    const float* Bg = B + b_r * ldb + bn + b_c4;

    int nk = K >> 5;

#pragma unroll
    for (int st = 0; st < 2; st++) {
        float* As = sm + st * A_STG;
        float* Bs = sm + B_OFF + st * B_STG;
#pragma unroll
        for (int rr = 0; rr < 4; rr++)
            cpa16(&As[(a_r + rr * 32) * AS_LD + a_c4], Ag + rr * 32 * lda + st * 32);
#pragma unroll
        for (int rr = 0; rr < 4; rr++)
            cpa16(&Bs[(b_r + rr * 8) * BS_LD + b_c4], Bg + (st * 32 + rr * 8) * ldb);
        cpa_commit();
    }

    float acc[4][4][4];
#pragma unroll
    for (int i = 0; i < 4; i++)
#pragma unroll
        for (int j = 0; j < 4; j++)
#pragma unroll
            for (int x = 0; x < 4; x++) acc[i][j][x] = 0.f;

    for (int kt = 0; kt < nk; kt++) {
        if (kt + 1 < nk) cpa_wait<1>(); else cpa_wait<0>();
        __syncthreads();

        if (kt + 2 < nk) {
            int st = (kt + 2) % 3;
            float* As = sm + st * A_STG;
            float* Bs = sm + B_OFF + st * B_STG;
            int k0 = (kt + 2) * 32;
#pragma unroll
            for (int rr = 0; rr < 4; rr++)
                cpa16(&As[(a_r + rr * 32) * AS_LD + a_c4], Ag + rr * 32 * lda + k0);
#pragma unroll
            for (int rr = 0; rr < 4; rr++)
                cpa16(&Bs[(b_r + rr * 8) * BS_LD + b_c4], Bg + (k0 + rr * 8) * ldb);
            cpa_commit();
        }

        const float* As = sm + (kt % 3) * A_STG;
        const float* Bs = sm + B_OFF + (kt % 3) * B_STG;
#pragma unroll
        for (int ks = 0; ks < 4; ks++) {
            int k0 = ks * 8;
            uint32_t af[4][4], bf[4][2];
#pragma unroll
            for (int i = 0; i < 4; i++) {
                int m = mw + i * 16 + g;
                af[i][0] = __float_as_uint(As[m * AS_LD + k0 + cq]);
                af[i][1] = __float_as_uint(As[(m + 8) * AS_LD + k0 + cq]);
                af[i][2] = __float_as_uint(As[m * AS_LD + k0 + cq + 4]);
                af[i][3] = __float_as_uint(As[(m + 8) * AS_LD + k0 + cq + 4]);
            }
#pragma unroll
            for (int j = 0; j < 4; j++) {
                int n = nw + j * 8 + g;
                bf[j][0] = __float_as_uint(Bs[(k0 + cq) * BS_LD + n]);
                bf[j][1] = __float_as_uint(Bs[(k0 + cq + 4) * BS_LD + n]);
            }
#pragma unroll
            for (int i = 0; i < 4; i++)
#pragma unroll
                for (int j = 0; j < 4; j++)
                    mma_tf32(acc[i][j], af[i], bf[j]);
        }
    }

#pragma unroll
    for (int i = 0; i < 4; i++) {
        int m0 = bm + mw + i * 16 + g;
#pragma unroll
        for (int j = 0; j < 4; j++) {
            int n = bn + nw + j * 8 + 2 * cq;
            float b0 = 0.f, b1 = 0.f;
            if (bias) { b0 = bias[n]; b1 = bias[n + 1]; }
            float v00 = acc[i][j][0] + b0, v01 = acc[i][j][1] + b1;
            float v10 = acc[i][j][2] + b0, v11 = acc[i][j][3] + b1;
            if (rnd) { v00 = tf32r(v00); v01 = tf32r(v01); v10 = tf32r(v10); v11 = tf32r(v11); }
            float2 lo = { v00, v01 }, hi = { v10, v11 };
            *(float2*)&C[m0 * ldc + n] = lo;
            *(float2*)&C[(m0 + 8) * ldc + n] = hi;
        }
    }
}

// ---------------- launch 2: conv+silu AND dt-gemm (fused) ------------------
// x < BB*LL: conv role (288 threads); else dt role (256 active)
__global__ void __launch_bounds__(288) conv_dt(
    const float* __restrict__ fw, const float* __restrict__ fb,
    const float* __restrict__ cw_, const float* __restrict__ cb,
    const float* __restrict__ fWin, const float* __restrict__ cWin,
    const float* __restrict__ fdtb, const float* __restrict__ cdtb,
    const float* __restrict__ fAl,  const float* __restrict__ cAl)
{
    int br = blockIdx.y;
    int tid = threadIdx.x;

    if (blockIdx.x < BB * LL) {
        // ---- conv role ----
        const float* w = br ? cw_ : fw;
        const float* bias = br ? cb : fb;
        int row = blockIdx.x;
        int b = row >> 11;
        int l = row & 2047;
        int c4 = tid * 4;

        float4 w0 = *(const float4*)(w + c4 * 4);
        float4 w1 = *(const float4*)(w + c4 * 4 + 4);
        float4 w2 = *(const float4*)(w + c4 * 4 + 8);
        float4 w3 = *(const float4*)(w + c4 * 4 + 12);
        float4 acc = *(const float4*)(bias + c4);

        const float* zbase = g_zx[br] + (size_t)(b * LL) * ZXW + DIN + c4;
#pragma unroll
        for (int j = 0; j < 4; j++) {
            int ls = l - 3 + j;
            if (ls >= 0) {
                float4 x = *(const float4*)(zbase + (size_t)ls * ZXW);
                acc.x += x.x * ((const float*)&w0)[j];
                acc.y += x.y * ((const float*)&w1)[j];
                acc.z += x.z * ((const float*)&w2)[j];
                acc.w += x.w * ((const float*)&w3)[j];
            }
        }
        float4 outv = { silu(acc.x), silu(acc.y), silu(acc.z), silu(acc.w) };
        *(float4*)(g_xbc[br] + (size_t)blockIdx.x * DXBC + c4) = outv;
        return;
    }

    // ---- dt role ----
    const float* Win = br ? cWin : fWin;
    const float* dtb = br ? cdtb : fdtb;
    const float* Alog = br ? cAl : fAl;
    const float* u = g_u[br];

    __shared__ float Ws[512][16];
    for (int i = tid; i < 512 * 16; i += 288) {
        int k = i >> 4, h = i & 15;
        Ws[k][h] = Win[k * WIN_LD + ZXW + h];
    }
    __syncthreads();
    if (tid >= 256) return;

    int rib = tid >> 4;
    int h   = tid & 15;
    int row = (blockIdx.x - BB * LL) * 16 + rib;
    const float* arow = u + row * DM;

    float a0 = 0.f, a1 = 0.f, a2 = 0.f, a3 = 0.f;
#pragma unroll 4
    for (int k = 0; k < 512; k += 4) {
        a0 += arow[k]     * Ws[k][h];
        a1 += arow[k + 1] * Ws[k + 1][h];
        a2 += arow[k + 2] * Ws[k + 2][h];
        a3 += arow[k + 3] * Ws[k + 3][h];
    }
    float acc = dtb[h] + ((a0 + a1) + (a2 + a3));

    float dt = acc > 20.f ? acc : log1pf(expf(acc));
    g_dtT[br][h * (BB * LL) + row] = dt;
    g_dAT[br][h * (BB * LL) + row] = expf(-expf(Alog[h]) * dt);
}

// ---------------- launch 3: SSD scan, register-resident, p-split -----------
// 256 blocks = (br, b, h, p-half); 128 threads; thread = 2p x 8n.
__global__ void __launch_bounds__(128) scan_kernel(const float* __restrict__ fD,
                                                   const float* __restrict__ cD)
{
    int blk = blockIdx.x;            // 256 = 2 * 4 * 16 * 2
    int ph = blk & 1;
    int h = (blk >> 1) & 15;
    int b = (blk >> 5) & 3;
    int br = blk >> 7;
    const float* xbc = g_xbc[br];
    const float* dtT = g_dtT[br] + h * (BB * LL);
    const float* dAT = g_dAT[br] + h * (BB * LL);
    float Dh = (br ? cD : fD)[h];
    float* yp = g_y[br];

    int w = threadIdx.x >> 5;
    int lane = threadIdx.x & 31;
    int p_sub = lane >> 3, ng = lane & 7;
    int p0 = ph * 32 + w * 8 + p_sub * 2;   // 2 p's: p0, p0+1
    int n0 = ng * 8;

    const size_t rowbase = (size_t)b * LL;
    const float* xptr = xbc + h * 64 + p0;
    const float* bptr = xbc + 1024 + n0;
    const float* cptr = xbc + 1088 + n0;

    float2 X[4];
    float4 Bl[4], Bh[4], Cl[4], Ch[4];

#define SCAN_LOAD(s, l) do { \
        size_t off = (rowbase + (l)) * DXBC; \
        X[s]  = *(const float2*)(xptr + off); \
        Bl[s] = *(const float4*)(bptr + off); \
        Bh[s] = *(const float4*)(bptr + off + 4); \
        Cl[s] = *(const float4*)(cptr + off); \
        Ch[s] = *(const float4*)(cptr + off + 4); \
    } while (0)

#pragma unroll
    for (int s = 0; s < 4; s++) SCAN_LOAD(s, s);

    float4 dt4 = *(const float4*)(dtT + rowbase);
    float4 da4 = *(const float4*)(dAT + rowbase);

    float hs[2][8];
#pragma unroll
    for (int j = 0; j < 2; j++)
#pragma unroll
        for (int k = 0; k < 8; k++) hs[j][k] = 0.f;

    for (int l = 0; l < LL; l += 4) {
        float4 dtc = dt4, dac = da4;
        if (l + 4 < LL) {
            dt4 = *(const float4*)(dtT + rowbase + l + 4);
            da4 = *(const float4*)(dAT + rowbase + l + 4);
        }
#pragma unroll
        for (int s = 0; s < 4; s++) {
            float dtv = ((const float*)&dtc)[s];
            float dav = ((const float*)&dac)[s];
            float2 xv = X[s];
            float4 b0 = Bl[s], b1 = Bh[s], c0 = Cl[s], c1 = Ch[s];
            if (l + s + 4 < LL) SCAN_LOAD(s, l + s + 4);

            float accv[2];
#pragma unroll
            for (int j = 0; j < 2; j++) {
                float xj = ((const float*)&xv)[j];
                float dtx = dtv * xj;
                float* hj = hs[j];
                float a;
                hj[0] = hj[0] * dav + dtx * b0.x; a  = hj[0] * c0.x;
                hj[1] = hj[1] * dav + dtx * b0.y; a += hj[1] * c0.y;
                hj[2] = hj[2] * dav + dtx * b0.z; a += hj[2] * c0.z;
                hj[3] = hj[3] * dav + dtx * b0.w; a += hj[3] * c0.w;
                hj[4] = hj[4] * dav + dtx * b1.x; a += hj[4] * c1.x;
                hj[5] = hj[5] * dav + dtx * b1.y; a += hj[5] * c1.y;
                hj[6] = hj[6] * dav + dtx * b1.z; a += hj[6] * c1.z;
                hj[7] = hj[7] * dav + dtx * b1.w; a += hj[7] * c1.w;
                accv[j] = a;
            }
#pragma unroll
            for (int j = 0; j < 2; j++) accv[j] += __shfl_xor_sync(0xffffffffu, accv[j], 1);
#pragma unroll
            for (int j = 0; j < 2; j++) accv[j] += __shfl_xor_sync(0xffffffffu, accv[j], 2);
#pragma unroll
            for (int j = 0; j < 2; j++) accv[j] += __shfl_xor_sync(0xffffffffu, accv[j], 4);

            if (ng == 0) {
                float2 o = { accv[0] + Dh * xv.x, accv[1] + Dh * xv.y };
                *(float2*)(yp + (rowbase + l + s) * DIN + h * HD + p0) = o;
            }
        }
    }
#undef SCAN_LOAD
}

// ---------------- y * silu(z) + rmsnorm (last LQ tokens, tf32 out) ---------
__global__ void yz_norm(const float* __restrict__ fnw, const float* __restrict__ cnw)
{
    int row = blockIdx.x;            // 2 * 4 * 1024
    int br = row >> 12;
    int r = row & 4095;
    int b = r >> 10;
    int lq = r & 1023;
    int l = lq + LQ;
    const float* nw = br ? cnw : fnw;
    const float* yrow = g_y[br] + (b * LL + l) * DIN;
    const float* zrow = g_zx[br] + (b * LL + l) * ZXW;

    int t = threadIdx.x;             // 256
    float v[4];
    float ss = 0.f;
#pragma unroll
    for (int i = 0; i < 4; i++) {
        int idx = t + i * 256;
        float z = zrow[idx];
        float val = yrow[idx] * silu(z);
        v[i] = val;
        ss += val * val;
    }

    __shared__ float red[8];
#pragma unroll
    for (int o = 16; o > 0; o >>= 1) ss += __shfl_xor_sync(0xffffffffu, ss, o);
    if ((t & 31) == 0) red[t >> 5] = ss;
    __syncthreads();
    float total = 0.f;
#pragma unroll
    for (int i = 0; i < 8; i++) total += red[i];
    float scale = rsqrtf(total / (float)DIN + 1e-5f);

    float* dst = g_nrm[br] + ((b << 10) + lq) * DIN;
#pragma unroll
    for (int i = 0; i < 4; i++) {
        int idx = t + i * 256;
        dst[idx] = tf32r(v[i] * scale * nw[idx]);
    }
}

// ---------------- launch ----------------------------------------------------
extern "C" void kernel_launch(void* const* d_in, const int* in_sizes, int n_in,
                              void* d_out, int out_size)
{
    const float* query   = (const float*)d_in[0];
    const float* kv      = (const float*)d_in[1];
    const float* fnorm_w = (const float*)d_in[2];
    const float* cnorm_w = (const float*)d_in[3];
    const float* f_Win   = (const float*)d_in[4];
    const float* f_convw = (const float*)d_in[5];
    const float* f_convb = (const float*)d_in[6];
    const float* f_dtb   = (const float*)d_in[7];
    const float* f_Alog  = (const float*)d_in[8];
    const float* f_D     = (const float*)d_in[9];
    const float* f_normw = (const float*)d_in[10];
    const float* f_Wout  = (const float*)d_in[11];
    const float* c_Win   = (const float*)d_in[12];
    const float* c_convw = (const float*)d_in[13];
    const float* c_convb = (const float*)d_in[14];
    const float* c_dtb   = (const float*)d_in[15];
    const float* c_Alog  = (const float*)d_in[16];
    const float* c_D     = (const float*)d_in[17];
    const float* c_normw = (const float*)d_in[18];
    const float* c_Wout  = (const float*)d_in[19];
    const float* outp_w  = (const float*)d_in[20];
    const float* outp_b  = (const float*)d_in[21];
    float* out = (float*)d_out;

    float *uP32, *zxP, *nrmP, *fsP, *win32P, *wout32P, *wo32P;
    cudaGetSymbolAddress((void**)&uP32,   g_u32);
    cudaGetSymbolAddress((void**)&zxP,    g_zx);
    cudaGetSymbolAddress((void**)&nrmP,   g_nrm);
    cudaGetSymbolAddress((void**)&fsP,    g_fs);
    cudaGetSymbolAddress((void**)&win32P, g_win32);
    cudaGetSymbolAddress((void**)&wout32P,g_wout32);
    cudaGetSymbolAddress((void**)&wo32P,  g_wo32);

    cudaFuncSetAttribute(gemm_tf32, cudaFuncAttributeMaxDynamicSharedMemorySize, GEMM_SMEM);

    float* u32_f = uP32;
    float* u32_c = uP32 + BB * LL * DM;
    float* zx_f = zxP;
    float* zx_c = zxP + BB * LL * ZXW;
    float* nrm_f = nrmP;
    float* nrm_c = nrmP + BB * LQ * DIN;
    float* win_f = win32P;
    float* win_c = win32P + DM * ZXW;
    float* wout_f = wout32P;
    float* wout_c = wout32P + DIN * DM;

    // (0) input rmsnorm + weight cvt (fused)
    {
        dim3 grid(2 * BB * LL, 2);
        prep_cvt<<<grid, 128>>>(query, kv, fnorm_w, cnorm_w,
                                f_Win, c_Win, f_Wout, c_Wout, outp_w);
    }

    // (1) in_proj GEMMs: (8192 x 512) @ (512 x 2176)
    {
        dim3 grid(ZXW / 128, (BB * LL) / 128, 2);
        gemm_tf32<<<grid, 256, GEMM_SMEM>>>(u32_f, u32_c, win_f, win_c, zx_f, zx_c,
                                            nullptr, BB * LL, ZXW, DM, DM, ZXW, ZXW, 0);
    }

    // (2) conv+silu + dt (fused)
    {
        dim3 grid(BB * LL + (BB * LL) / 16, 2);
        conv_dt<<<grid, 288>>>(f_convw, f_convb, c_convw, c_convb,
                               f_Win, c_Win, f_dtb, c_dtb, f_Alog, c_Alog);
    }

    // (3) register-resident scan, p-split (capture target)
    scan_kernel<<<256, 128>>>(f_D, c_D);

    // (4) gate + rmsnorm (only the output slice)
    yz_norm<<<2 * BB * LQ, 256>>>(f_normw, c_normw);

    // (5) out-projection GEMMs: (4096 x 1024) @ (1024 x 512)
    {
        dim3 grid(DM / 128, (BB * LQ) / 128, 2);
        gemm_tf32<<<grid, 256, GEMM_SMEM>>>(nrm_f, nrm_c, wout_f, wout_c,
                                            fsP, out + BB * LQ * DM,
                                            nullptr, BB * LQ, DM, DIN, DIN, DM, DM, 1);
    }

    // (6) factual final projection with bias: (4096 x 512) @ (512 x 512) + b
    {
        dim3 grid(DM / 128, (BB * LQ) / 128, 1);
        gemm_tf32<<<grid, 256, GEMM_SMEM>>>(fsP, fsP, wo32P, wo32P, out, out,
                                            outp_b, BB * LQ, DM, DM, DM, DM, DM, 0);
    }
}

// round 12
// speedup vs baseline: 1.0313x; 1.0313x over previous
#include <cuda_runtime.h>
#include <math.h>
#include <stdint.h>

#define BB 4
#define LL 2048
#define LQ 1024
#define DM 512
#define DIN 1024
#define DSTATE 64
#define NH 16
#define HD 64
#define DXBC 1152
#define ZXW 2176      // z + xBC columns kept in g_zx (row stride)
#define WIN_LD 2192   // full in_proj width (z + xBC + dt)

// ---------------- scratch (device globals; allocation-free) ----------------
__device__ float g_u[2][BB*LL*DM];        // rmsnormed inputs (fp32, for dt path)
__device__ float g_u32[2][BB*LL*DM];      // rmsnormed inputs (tf32-rounded, GEMM A)
__device__ float g_zx[2][BB*LL*ZXW];      // in_proj outputs (z + xBC)
__device__ float g_xbc[2][BB*LL*DXBC];    // conv+silu outputs
__device__ float g_dtT[2][NH*BB*LL];      // dt transposed [h][row]
__device__ float g_dAT[2][NH*BB*LL];      // dA transposed [h][row]
__device__ float g_y[2][BB*LL*DIN];       // scan outputs, n-half 0 (+D*x)
__device__ float g_y2[2][BB*LL*DIN];      // scan outputs, n-half 1
__device__ float g_nrm[2][BB*LQ*DIN];     // gated rmsnorm (tf32-rounded)
__device__ float g_fs[BB*LQ*DM];          // factual pre-out-proj (tf32-rounded)
__device__ float g_win32[2][DM*ZXW];      // tf32 weights
__device__ float g_wout32[2][DIN*DM];
__device__ float g_wo32[DM*DM];

// ---------------- helpers ----------------
__device__ __forceinline__ float silu(float x) { return x / (1.f + expf(-x)); }

__device__ __forceinline__ uint32_t f2tf32(float x) {
    uint32_t r;
    asm("cvt.rna.tf32.f32 %0, %1;" : "=r"(r) : "f"(x));
    return r;
}
__device__ __forceinline__ float tf32r(float x) { return __uint_as_float(f2tf32(x)); }

__device__ __forceinline__ void mma_tf32(float* c, const uint32_t* a, const uint32_t* b) {
    asm volatile("mma.sync.aligned.m16n8k8.row.col.f32.tf32.tf32.f32 "
        "{%0,%1,%2,%3}, {%4,%5,%6,%7}, {%8,%9}, {%0,%1,%2,%3};"
        : "+f"(c[0]), "+f"(c[1]), "+f"(c[2]), "+f"(c[3])
        : "r"(a[0]), "r"(a[1]), "r"(a[2]), "r"(a[3]), "r"(b[0]), "r"(b[1]));
}

__device__ __forceinline__ void cpa16(float* dst, const float* src) {
    uint32_t d = (uint32_t)__cvta_generic_to_shared(dst);
    asm volatile("cp.async.cg.shared.global [%0], [%1], 16;" :: "r"(d), "l"(src));
}
__device__ __forceinline__ void cpa_commit() { asm volatile("cp.async.commit_group;"); }
template<int N> __device__ __forceinline__ void cpa_wait() {
    asm volatile("cp.async.wait_group %0;" :: "n"(N));
}

// ---------------- launch 0: input rmsnorm + weight cvt (fused) -------------
#define CVT_TOT (2*DM*ZXW + 2*DIN*DM + DM*DM)
__global__ void __launch_bounds__(128) prep_cvt(
    const float* __restrict__ q, const float* __restrict__ kv,
    const float* __restrict__ fw, const float* __restrict__ cw,
    const float* __restrict__ fWin, const float* __restrict__ cWin,
    const float* __restrict__ fWout, const float* __restrict__ cWout,
    const float* __restrict__ oW)
{
    int t = threadIdx.x;
    if (blockIdx.y == 1) {
        for (int i = blockIdx.x * 128 + t; i < CVT_TOT; i += 16384 * 128) {
            int j = i;
            if (j < 2 * DM * ZXW) {
                int reg = j / (DM * ZXW);
                int k = j - reg * (DM * ZXW);
                const float* s = reg ? cWin : fWin;
                int r = k / ZXW, c = k - r * ZXW;
                g_win32[reg][k] = tf32r(s[r * WIN_LD + c]);
            } else if ((j -= 2 * DM * ZXW) < 2 * DIN * DM) {
                int reg = j / (DIN * DM);
                int k = j - reg * (DIN * DM);
                g_wout32[reg][k] = tf32r((reg ? cWout : fWout)[k]);
            } else {
                j -= 2 * DIN * DM;
                g_wo32[j] = tf32r(oW[j]);
            }
        }
        return;
    }

    int row = blockIdx.x;            // 2 * 4 * 2048 rows
    int br  = row >> 13;
    int r   = row & 8191;
    int b   = r >> 11;
    int l   = r & 2047;
    const float* src;
    if (l < LQ) {
        int li = (br == 0) ? l : (LQ - 1 - l);
        src = kv + (b * LQ + li) * DM;
    } else {
        src = q + (b * LQ + (l - LQ)) * DM;
    }
    const float* w = br ? cw : fw;

    float v[4];
    float ss = 0.f;
#pragma unroll
    for (int i = 0; i < 4; i++) { v[i] = src[t + i * 128]; ss += v[i] * v[i]; }

    __shared__ float red[4];
#pragma unroll
    for (int o = 16; o > 0; o >>= 1) ss += __shfl_xor_sync(0xffffffffu, ss, o);
    if ((t & 31) == 0) red[t >> 5] = ss;
    __syncthreads();
    float total = red[0] + red[1] + red[2] + red[3];
    float scale = rsqrtf(total / (float)DM + 1e-5f);

    float* dst   = g_u[br]   + (b * LL + l) * DM;
    float* dst32 = g_u32[br] + (b * LL + l) * DM;
#pragma unroll
    for (int i = 0; i < 4; i++) {
        int idx = t + i * 128;
        float val = v[i] * scale * w[idx];
        dst[idx] = val;
        dst32[idx] = tf32r(val);
    }
}

// ---------------- TF32 GEMM: 128x128x32 tile, 8 warps (64x32), 3-stage -----
#define AS_LD 36
#define BS_LD 136
#define A_STG (128 * AS_LD)    // 4608 floats
#define B_STG (32 * BS_LD)     // 4352 floats
#define B_OFF (3 * A_STG)
#define GEMM_SMEM ((3 * (A_STG + B_STG)) * 4)

__global__ void __launch_bounds__(256) gemm_tf32(
    const float* __restrict__ A0, const float* __restrict__ A1,
    const float* __restrict__ B0, const float* __restrict__ B1,
    float* __restrict__ C0, float* __restrict__ C1,
    const float* __restrict__ bias,
    int M, int N, int K, int lda, int ldb, int ldc, int roundMask)
{
    extern __shared__ float sm[];
    int z = blockIdx.z;
    const float* A = z ? A1 : A0;
    const float* B = z ? B1 : B0;
    float* C = z ? C1 : C0;
    bool rnd = (roundMask >> z) & 1;

    int tid = threadIdx.x;
    int bm = blockIdx.y * 128, bn = blockIdx.x * 128;

    int w = tid >> 5;
    int lane = tid & 31;
    int g = lane >> 2, cq = lane & 3;
    int mw = (w & 1) * 64;
    int nw = (w >> 1) * 32;

    int a_r = tid >> 3, a_c4 = (tid & 7) * 4;
    int b_r = tid >> 5, b_c4 = (tid & 31) * 4;

    const float* Ag = A + (bm + a_r) * lda + a_c4;
    const float* Bg = B + b_r * ldb + bn + b_c4;

    int nk = K >> 5;

#pragma unroll
    for (int st = 0; st < 2; st++) {
        float* As = sm + st * A_STG;
        float* Bs = sm + B_OFF + st * B_STG;
#pragma unroll
        for (int rr = 0; rr < 4; rr++)
            cpa16(&As[(a_r + rr * 32) * AS_LD + a_c4], Ag + rr * 32 * lda + st * 32);
#pragma unroll
        for (int rr = 0; rr < 4; rr++)
            cpa16(&Bs[(b_r + rr * 8) * BS_LD + b_c4], Bg + (st * 32 + rr * 8) * ldb);
        cpa_commit();
    }

    float acc[4][4][4];
#pragma unroll
    for (int i = 0; i < 4; i++)
#pragma unroll
        for (int j = 0; j < 4; j++)
#pragma unroll
            for (int x = 0; x < 4; x++) acc[i][j][x] = 0.f;

    for (int kt = 0; kt < nk; kt++) {
        if (kt + 1 < nk) cpa_wait<1>(); else cpa_wait<0>();
        __syncthreads();

        if (kt + 2 < nk) {
            int st = (kt + 2) % 3;
            float* As = sm + st * A_STG;
            float* Bs = sm + B_OFF + st * B_STG;
            int k0 = (kt + 2) * 32;
#pragma unroll
            for (int rr = 0; rr < 4; rr++)
                cpa16(&As[(a_r + rr * 32) * AS_LD + a_c4], Ag + rr * 32 * lda + k0);
#pragma unroll
            for (int rr = 0; rr < 4; rr++)
                cpa16(&Bs[(b_r + rr * 8) * BS_LD + b_c4], Bg + (k0 + rr * 8) * ldb);
            cpa_commit();
        }

        const float* As = sm + (kt % 3) * A_STG;
        const float* Bs = sm + B_OFF + (kt % 3) * B_STG;
#pragma unroll
        for (int ks = 0; ks < 4; ks++) {
            int k0 = ks * 8;
            uint32_t af[4][4], bf[4][2];
#pragma unroll
            for (int i = 0; i < 4; i++) {
                int m = mw + i * 16 + g;
                af[i][0] = __float_as_uint(As[m * AS_LD + k0 + cq]);
                af[i][1] = __float_as_uint(As[(m + 8) * AS_LD + k0 + cq]);
                af[i][2] = __float_as_uint(As[m * AS_LD + k0 + cq + 4]);
                af[i][3] = __float_as_uint(As[(m + 8) * AS_LD + k0 + cq + 4]);
            }
#pragma unroll
            for (int j = 0; j < 4; j++) {
                int n = nw + j * 8 + g;
                bf[j][0] = __float_as_uint(Bs[(k0 + cq) * BS_LD + n]);
                bf[j][1] = __float_as_uint(Bs[(k0 + cq + 4) * BS_LD + n]);
            }
#pragma unroll
            for (int i = 0; i < 4; i++)
#pragma unroll
                for (int j = 0; j < 4; j++)
                    mma_tf32(acc[i][j], af[i], bf[j]);
        }
    }

#pragma unroll
    for (int i = 0; i < 4; i++) {
        int m0 = bm + mw + i * 16 + g;
#pragma unroll
        for (int j = 0; j < 4; j++) {
            int n = bn + nw + j * 8 + 2 * cq;
            float b0 = 0.f, b1 = 0.f;
            if (bias) { b0 = bias[n]; b1 = bias[n + 1]; }
            float v00 = acc[i][j][0] + b0, v01 = acc[i][j][1] + b1;
            float v10 = acc[i][j][2] + b0, v11 = acc[i][j][3] + b1;
            if (rnd) { v00 = tf32r(v00); v01 = tf32r(v01); v10 = tf32r(v10); v11 = tf32r(v11); }
            float2 lo = { v00, v01 }, hi = { v10, v11 };
            *(float2*)&C[m0 * ldc + n] = lo;
            *(float2*)&C[(m0 + 8) * ldc + n] = hi;
        }
    }
}

// ---------------- launch 2: conv+silu AND dt-gemm (fused) ------------------
__global__ void __launch_bounds__(288) conv_dt(
    const float* __restrict__ fw, const float* __restrict__ fb,
    const float* __restrict__ cw_, const float* __restrict__ cb,
    const float* __restrict__ fWin, const float* __restrict__ cWin,
    const float* __restrict__ fdtb, const float* __restrict__ cdtb,
    const float* __restrict__ fAl,  const float* __restrict__ cAl)
{
    int br = blockIdx.y;
    int tid = threadIdx.x;

    if (blockIdx.x < BB * LL) {
        const float* w = br ? cw_ : fw;
        const float* bias = br ? cb : fb;
        int row = blockIdx.x;
        int b = row >> 11;
        int l = row & 2047;
        int c4 = tid * 4;

        float4 w0 = *(const float4*)(w + c4 * 4);
        float4 w1 = *(const float4*)(w + c4 * 4 + 4);
        float4 w2 = *(const float4*)(w + c4 * 4 + 8);
        float4 w3 = *(const float4*)(w + c4 * 4 + 12);
        float4 acc = *(const float4*)(bias + c4);

        const float* zbase = g_zx[br] + (size_t)(b * LL) * ZXW + DIN + c4;
#pragma unroll
        for (int j = 0; j < 4; j++) {
            int ls = l - 3 + j;
            if (ls >= 0) {
                float4 x = *(const float4*)(zbase + (size_t)ls * ZXW);
                acc.x += x.x * ((const float*)&w0)[j];
                acc.y += x.y * ((const float*)&w1)[j];
                acc.z += x.z * ((const float*)&w2)[j];
                acc.w += x.w * ((const float*)&w3)[j];
            }
        }
        float4 outv = { silu(acc.x), silu(acc.y), silu(acc.z), silu(acc.w) };
        *(float4*)(g_xbc[br] + (size_t)blockIdx.x * DXBC + c4) = outv;
        return;
    }

    const float* Win = br ? cWin : fWin;
    const float* dtb = br ? cdtb : fdtb;
    const float* Alog = br ? cAl : fAl;
    const float* u = g_u[br];

    __shared__ float Ws[512][16];
    for (int i = tid; i < 512 * 16; i += 288) {
        int k = i >> 4, h = i & 15;
        Ws[k][h] = Win[k * WIN_LD + ZXW + h];
    }
    __syncthreads();
    if (tid >= 256) return;

    int rib = tid >> 4;
    int h   = tid & 15;
    int row = (blockIdx.x - BB * LL) * 16 + rib;
    const float* arow = u + row * DM;

    float a0 = 0.f, a1 = 0.f, a2 = 0.f, a3 = 0.f;
#pragma unroll 4
    for (int k = 0; k < 512; k += 4) {
        a0 += arow[k]     * Ws[k][h];
        a1 += arow[k + 1] * Ws[k + 1][h];
        a2 += arow[k + 2] * Ws[k + 2][h];
        a3 += arow[k + 3] * Ws[k + 3][h];
    }
    float acc = dtb[h] + ((a0 + a1) + (a2 + a3));

    float dt = acc > 20.f ? acc : log1pf(expf(acc));
    g_dtT[br][h * (BB * LL) + row] = dt;
    g_dAT[br][h * (BB * LL) + row] = expf(-expf(Alog[h]) * dt);
}

// ---------------- launch 3: SSD scan, n-split + p-split, depth-8 prefetch --
// 512 blocks = (br, b, h, nh, ph); 128 threads; thread = 2p x 4n.
__global__ void __launch_bounds__(128) scan_kernel(const float* __restrict__ fD,
                                                   const float* __restrict__ cD)
{
    int blk = blockIdx.x;            // 512 = 2 * 4 * 16 * 2 * 2
    int ph = blk & 1;
    int nh = (blk >> 1) & 1;
    int h  = (blk >> 2) & 15;
    int b  = (blk >> 6) & 3;
    int br = blk >> 8;
    const float* xbc = g_xbc[br];
    const float* dtT = g_dtT[br] + h * (BB * LL);
    const float* dAT = g_dAT[br] + h * (BB * LL);
    float DhE = (nh == 0) ? (br ? cD : fD)[h] : 0.f;   // D*x added once (n-half 0)
    float* yp = nh ? g_y2[br] : g_y[br];

    int w = threadIdx.x >> 5;
    int lane = threadIdx.x & 31;
    int p_sub = lane >> 3, ng = lane & 7;
    int p0 = ph * 32 + w * 8 + p_sub * 2;   // 2 p's
    int n0 = nh * 32 + ng * 4;              // 4 n's

    const size_t rowbase = (size_t)b * LL;
    const float* xptr = xbc + h * 64 + p0;
    const float* bptr = xbc + 1024 + n0;
    const float* cptr = xbc + 1088 + n0;

    float2 X[8];
    float4 Bq[8], Cq[8];

#define SCAN_LOAD(s, l) do { \
        size_t off = (rowbase + (l)) * DXBC; \
        X[s]  = *(const float2*)(xptr + off); \
        Bq[s] = *(const float4*)(bptr + off); \
        Cq[s] = *(const float4*)(cptr + off); \
    } while (0)

#pragma unroll
    for (int s = 0; s < 8; s++) SCAN_LOAD(s, s);

    float4 dtA = *(const float4*)(dtT + rowbase);
    float4 dtB = *(const float4*)(dtT + rowbase + 4);
    float4 daA = *(const float4*)(dAT + rowbase);
    float4 daB = *(const float4*)(dAT + rowbase + 4);

    float h0[4], h1[4];
#pragma unroll
    for (int k = 0; k < 4; k++) { h0[k] = 0.f; h1[k] = 0.f; }

    for (int l = 0; l < LL; l += 8) {
        float dts[8] = { dtA.x, dtA.y, dtA.z, dtA.w, dtB.x, dtB.y, dtB.z, dtB.w };
        float das[8] = { daA.x, daA.y, daA.z, daA.w, daB.x, daB.y, daB.z, daB.w };
        if (l + 8 < LL) {
            dtA = *(const float4*)(dtT + rowbase + l + 8);
            dtB = *(const float4*)(dtT + rowbase + l + 12);
            daA = *(const float4*)(dAT + rowbase + l + 8);
            daB = *(const float4*)(dAT + rowbase + l + 12);
        }
#pragma unroll
        for (int s = 0; s < 8; s++) {
            float dtv = dts[s], dav = das[s];
            float2 xv = X[s];
            float4 bq = Bq[s], cq = Cq[s];
            if (l + s + 8 < LL) SCAN_LOAD(s, l + s + 8);

            float dtx0 = dtv * xv.x, dtx1 = dtv * xv.y;
            float a0, a1;
            h0[0] = h0[0] * dav + dtx0 * bq.x; a0  = h0[0] * cq.x;
            h0[1] = h0[1] * dav + dtx0 * bq.y; a0 += h0[1] * cq.y;
            h0[2] = h0[2] * dav + dtx0 * bq.z; a0 += h0[2] * cq.z;
            h0[3] = h0[3] * dav + dtx0 * bq.w; a0 += h0[3] * cq.w;
            h1[0] = h1[0] * dav + dtx1 * bq.x; a1  = h1[0] * cq.x;
            h1[1] = h1[1] * dav + dtx1 * bq.y; a1 += h1[1] * cq.y;
            h1[2] = h1[2] * dav + dtx1 * bq.z; a1 += h1[2] * cq.z;
            h1[3] = h1[3] * dav + dtx1 * bq.w; a1 += h1[3] * cq.w;

            a0 += __shfl_xor_sync(0xffffffffu, a0, 1);
            a1 += __shfl_xor_sync(0xffffffffu, a1, 1);
            a0 += __shfl_xor_sync(0xffffffffu, a0, 2);
            a1 += __shfl_xor_sync(0xffffffffu, a1, 2);
            a0 += __shfl_xor_sync(0xffffffffu, a0, 4);
            a1 += __shfl_xor_sync(0xffffffffu, a1, 4);

            if (ng == 0) {
                float2 o = { a0 + DhE * xv.x, a1 + DhE * xv.y };
                *(float2*)(yp + (rowbase + l + s) * DIN + h * HD + p0) = o;
            }
        }
    }
#undef SCAN_LOAD
}

// ---------------- y*silu(z) + rmsnorm (sums the two n-half partials) -------
__global__ void yz_norm(const float* __restrict__ fnw, const float* __restrict__ cnw)
{
    int row = blockIdx.x;            // 2 * 4 * 1024
    int br = row >> 12;
    int r = row & 4095;
    int b = r >> 10;
    int lq = r & 1023;
    int l = lq + LQ;
    const float* nw = br ? cnw : fnw;
    const float* yrow  = g_y[br]  + (b * LL + l) * DIN;
    const float* y2row = g_y2[br] + (b * LL + l) * DIN;
    const float* zrow  = g_zx[br] + (b * LL + l) * ZXW;

    int t = threadIdx.x;             // 256
    float v[4];
    float ss = 0.f;
#pragma unroll
    for (int i = 0; i < 4; i++) {
        int idx = t + i * 256;
        float z = zrow[idx];
        float val = (yrow[idx] + y2row[idx]) * silu(z);
        v[i] = val;
        ss += val * val;
    }

    __shared__ float red[8];
#pragma unroll
    for (int o = 16; o > 0; o >>= 1) ss += __shfl_xor_sync(0xffffffffu, ss, o);
    if ((t & 31) == 0) red[t >> 5] = ss;
    __syncthreads();
    float total = 0.f;
#pragma unroll
    for (int i = 0; i < 8; i++) total += red[i];
    float scale = rsqrtf(total / (float)DIN + 1e-5f);

    float* dst = g_nrm[br] + ((b << 10) + lq) * DIN;
#pragma unroll
    for (int i = 0; i < 4; i++) {
        int idx = t + i * 256;
        dst[idx] = tf32r(v[i] * scale * nw[idx]);
    }
}

// ---------------- launch ----------------------------------------------------
extern "C" void kernel_launch(void* const* d_in, const int* in_sizes, int n_in,
                              void* d_out, int out_size)
{
    const float* query   = (const float*)d_in[0];
    const float* kv      = (const float*)d_in[1];
    const float* fnorm_w = (const float*)d_in[2];
    const float* cnorm_w = (const float*)d_in[3];
    const float* f_Win   = (const float*)d_in[4];
    const float* f_convw = (const float*)d_in[5];
    const float* f_convb = (const float*)d_in[6];
    const float* f_dtb   = (const float*)d_in[7];
    const float* f_Alog  = (const float*)d_in[8];
    const float* f_D     = (const float*)d_in[9];
    const float* f_normw = (const float*)d_in[10];
    const float* f_Wout  = (const float*)d_in[11];
    const float* c_Win   = (const float*)d_in[12];
    const float* c_convw = (const float*)d_in[13];
    const float* c_convb = (const float*)d_in[14];
    const float* c_dtb   = (const float*)d_in[15];
    const float* c_Alog  = (const float*)d_in[16];
    const float* c_D     = (const float*)d_in[17];
    const float* c_normw = (const float*)d_in[18];
    const float* c_Wout  = (const float*)d_in[19];
    const float* outp_w  = (const float*)d_in[20];
    const float* outp_b  = (const float*)d_in[21];
    float* out = (float*)d_out;

    float *uP32, *zxP, *nrmP, *fsP, *win32P, *wout32P, *wo32P;
    cudaGetSymbolAddress((void**)&uP32,   g_u32);
    cudaGetSymbolAddress((void**)&zxP,    g_zx);
    cudaGetSymbolAddress((void**)&nrmP,   g_nrm);
    cudaGetSymbolAddress((void**)&fsP,    g_fs);
    cudaGetSymbolAddress((void**)&win32P, g_win32);
    cudaGetSymbolAddress((void**)&wout32P,g_wout32);
    cudaGetSymbolAddress((void**)&wo32P,  g_wo32);

    cudaFuncSetAttribute(gemm_tf32, cudaFuncAttributeMaxDynamicSharedMemorySize, GEMM_SMEM);

    float* u32_f = uP32;
    float* u32_c = uP32 + BB * LL * DM;
    float* zx_f = zxP;
    float* zx_c = zxP + BB * LL * ZXW;
    float* nrm_f = nrmP;
    float* nrm_c = nrmP + BB * LQ * DIN;
    float* win_f = win32P;
    float* win_c = win32P + DM * ZXW;
    float* wout_f = wout32P;
    float* wout_c = wout32P + DIN * DM;

    // (0) input rmsnorm + weight cvt (fused)
    {
        dim3 grid(2 * BB * LL, 2);
        prep_cvt<<<grid, 128>>>(query, kv, fnorm_w, cnorm_w,
                                f_Win, c_Win, f_Wout, c_Wout, outp_w);
    }

    // (1) in_proj GEMMs: (8192 x 512) @ (512 x 2176)
    {
        dim3 grid(ZXW / 128, (BB * LL) / 128, 2);
        gemm_tf32<<<grid, 256, GEMM_SMEM>>>(u32_f, u32_c, win_f, win_c, zx_f, zx_c,
                                            nullptr, BB * LL, ZXW, DM, DM, ZXW, ZXW, 0);
    }

    // (2) conv+silu + dt (fused)
    {
        dim3 grid(BB * LL + (BB * LL) / 16, 2);
        conv_dt<<<grid, 288>>>(f_convw, f_convb, c_convw, c_convb,
                               f_Win, c_Win, f_dtb, c_dtb, f_Alog, c_Alog);
    }

    // (3) scan: n-split + p-split, deep prefetch (capture target)
    scan_kernel<<<512, 128>>>(f_D, c_D);

    // (4) gate + rmsnorm (sums partials; only the output slice)
    yz_norm<<<2 * BB * LQ, 256>>>(f_normw, c_normw);

    // (5) out-projection GEMMs: (4096 x 1024) @ (1024 x 512)
    {
        dim3 grid(DM / 128, (BB * LQ) / 128, 2);
        gemm_tf32<<<grid, 256, GEMM_SMEM>>>(nrm_f, nrm_c, wout_f, wout_c,
                                            fsP, out + BB * LQ * DM,
                                            nullptr, BB * LQ, DM, DIN, DIN, DM, DM, 1);
    }

    // (6) factual final projection with bias: (4096 x 512) @ (512 x 512) + b
    {
        dim3 grid(DM / 128, (BB * LQ) / 128, 1);
        gemm_tf32<<<grid, 256, GEMM_SMEM>>>(fsP, fsP, wo32P, wo32P, out, out,
                                            outp_b, BB * LQ, DM, DM, DM, DM, DM, 0);
    }
}